// round 9
// baseline (speedup 1.0000x reference)
#include <cuda_runtime.h>

// Inputs (metadata order):
// 0: y (B,4N) f32 | 1: Ic (B,) | 2: C (N,) | 3: g_Na | 4: E_Na | 5: g_K | 6: E_K
// 7: g_L | 8: E_L | 9: m_inf | 10: tau_m | 11: h_inf | 12: tau_h | 13: n_inf
// 14: tau_n | 15: g_C (N,N)
// Output: ydot (B,4N) followed by J (B,4N,4N), f32.

#define BATCH 256
#define NN    128   // N
#define E4    512   // 4*N
#define BPB   4     // batches per ydot block
#define YBLOCKS (BATCH / BPB)          // 64 ydot-role blocks (scheduled first)
#define JBLOCKS 16384                  // 16,777,216 float4 / 1024 per block

// ---------------------------------------------------------------------------
// streaming 128-bit store (evict-first: J is write-once)
// ---------------------------------------------------------------------------
__device__ __forceinline__ void stg_cs(float4* p, float4 v) {
    asm volatile("st.global.cs.v4.f32 [%0], {%1, %2, %3, %4};"
                 :: "l"(p), "f"(v.x), "f"(v.y), "f"(v.z), "f"(v.w)
                 : "memory");
}

// ===========================================================================
// ONE fused kernel.
//   blockIdx < YBLOCKS  : ydot role — coupling dot, ydot output, AND the
//                         diagonal float4s of J (needs S; address-disjoint
//                         from the jfill role's writes).
//   blockIdx >= YBLOCKS : jfill role — streams all NON-diagonal float4s of J.
// Diagonal float4 of batch b, row r lives at column-quad jq == (r>>2); the
// jfill role predicates that store off, the ydot role writes exactly those.
// ===========================================================================
__global__ void __launch_bounds__(256, 8) hh_fused_kernel(
    const float* __restrict__ y, const float* __restrict__ Ic,
    const float* __restrict__ C,
    const float* __restrict__ gNa, const float* __restrict__ ENa,
    const float* __restrict__ gK,  const float* __restrict__ EK,
    const float* __restrict__ gL,  const float* __restrict__ EL,
    const float* __restrict__ minf, const float* __restrict__ taum,
    const float* __restrict__ hinf, const float* __restrict__ tauh,
    const float* __restrict__ ninf, const float* __restrict__ taun,
    const float* __restrict__ gC,
    float* __restrict__ out_ydot,
    float* __restrict__ out_J)
{
    __shared__ float Gt[NN][33];       // padded gC column tile
    __shared__ float Wj[NN];           // invC[j]
    __shared__ float WVs[BPB][NN];     // invC[j] * V_b[j]
    __shared__ float red[4];

    int tid = threadIdx.x;

    if (blockIdx.x >= YBLOCKS) {
        // ------------------------------------------------------------------
        // jfill role: 1024 float4s per block, 4 coalesced stores per thread.
        // float4-idx layout: j = idx & 127; r = (idx>>7) & 511; b = idx>>16.
        // ------------------------------------------------------------------
        int base = (blockIdx.x - YBLOCKS) * 1024 + tid;
        int j = base & (NN - 1);
        float invCj = 1.0f / C[j];
        float4* out = reinterpret_cast<float4*>(out_J);

        #pragma unroll
        for (int k = 0; k < 4; k++) {
            int idx = base + k * 256;
            int r = (idx >> 7) & (E4 - 1);
            int rt = r & 3;          // warp-uniform
            int i  = r >> 2;

            float4 v = make_float4(0.f, 0.f, 0.f, 0.f);
            if (rt == 0)
                v.x = -gC[i * NN + j] * invCj;

            if (i != j)              // diagonal quad owned by ydot role
                stg_cs(out + idx, v);
        }
        return;
    }

    // ----------------------------------------------------------------------
    // ydot role: BPB batches per block.  All 256 threads help stage gC;
    // threads 0..127 own one neuron each.
    // ----------------------------------------------------------------------
    int b0 = blockIdx.x * BPB;
    int i  = tid;                    // neuron id (valid for tid < 128)
    int lane = tid & 31;
    int w8   = tid >> 5;             // warp id 0..7

    float invCi = 0.f;
    float V[BPB], m[BPB], h[BPB], n[BPB];

    if (tid < NN) {
        invCi = 1.0f / C[i];
        Wj[i] = invCi;
        #pragma unroll
        for (int bb = 0; bb < BPB; bb++) {
            float4 y4 = reinterpret_cast<const float4*>(y)[(b0 + bb) * NN + i];
            V[bb] = y4.x; m[bb] = y4.y; h[bb] = y4.z; n[bb] = y4.w;
            WVs[bb][i] = invCi * y4.x;
        }
    }
    __syncthreads();

    float rs = 0.0f;                 // sum_j g[i][j] * invC[j]  (batch-indep)
    float gv[BPB] = {0.f, 0.f, 0.f, 0.f};

    #pragma unroll
    for (int t = 0; t < 4; t++) {
        // all 256 threads stage columns [32t, 32t+32): 8 warps x 16 rows
        #pragma unroll 4
        for (int k = 0; k < 16; k++) {
            int row = k * 8 + w8;
            Gt[row][lane] = gC[row * NN + t * 32 + lane];
        }
        __syncthreads();

        if (tid < NN) {
            #pragma unroll 4
            for (int jj = 0; jj < 32; jj++) {
                float g = Gt[i][jj];
                int j = t * 32 + jj;
                rs += g * Wj[j];
                #pragma unroll
                for (int bb = 0; bb < BPB; bb++)
                    gv[bb] += g * WVs[bb][j];
            }
        }
        __syncthreads();
    }

    // block-reduce rs over threads 0..127 -> S (deterministic), broadcast
    if (tid < NN) {
        float tr = rs;
        #pragma unroll
        for (int o2 = 16; o2 > 0; o2 >>= 1)
            tr += __shfl_xor_sync(0xFFFFFFFFu, tr, o2);
        if (lane == 0) red[w8] = tr;       // w8 in 0..3 for tid<128
    }
    __syncthreads();

    if (tid >= NN) return;

    float S = red[0] + red[1] + red[2] + red[3];

    float ga = gNa[i], gk = gK[i], gl = gL[i];
    float eNa = ENa[i], eK = EK[i], eL = EL[i];
    float mi = minf[i], hi = hinf[i], ni = ninf[i];
    float itm = 1.0f / taum[i], ith = 1.0f / tauh[i], itn = 1.0f / taun[i];
    float gdiag = gC[i * NN + i];
    float4* outJ4 = reinterpret_cast<float4*>(out_J);

    #pragma unroll
    for (int bb = 0; bb < BPB; bb++) {
        int b = b0 + bb;
        float Vb = V[bb], mb = m[bb], hb = h[bb], nb = n[bb];
        float acc = Vb * rs - gv[bb];
        float m2 = mb * mb, m3 = m2 * mb;
        float n2 = nb * nb, n3 = n2 * nb, n4 = n3 * nb;
        float dNa = Vb - eNa, dK = Vb - eK;

        float Vdot = invCi * (-ga * m3 * hb * dNa
                              - gk * n4 * dK
                              - gl * (Vb - eL)
                              + Ic[b]) + acc;
        float4 o;
        o.x = Vdot;
        o.y = (mi - mb) * itm;
        o.z = (hi - hb) * ith;
        o.w = (ni - nb) * itn;
        reinterpret_cast<float4*>(out_ydot)[b * NN + i] = o;

        // ---- diagonal float4s of J for (b, i): rows 4i..4i+3, col-quad i ----
        int idx0 = b * (E4 * NN) + (4 * i) * NN + i;   // V row
        float4 dv;
        dv.x = -gdiag * invCi + S + invCi * (-gl - ga * hb * m3 - gk * n4);
        dv.y = -invCi * (3.0f * ga * hb * m2 * dNa);
        dv.z = -invCi * (ga * m3 * dNa);
        dv.w = -invCi * (4.0f * gk * n3 * dK);
        outJ4[idx0]            = dv;
        outJ4[idx0 + NN]       = make_float4(0.f, -itm, 0.f, 0.f);  // m row
        outJ4[idx0 + 2 * NN]   = make_float4(0.f, 0.f, -ith, 0.f);  // h row
        outJ4[idx0 + 3 * NN]   = make_float4(0.f, 0.f, 0.f, -itn);  // n row
    }
}

// ---------------------------------------------------------------------------
extern "C" void kernel_launch(void* const* d_in, const int* in_sizes, int n_in,
                              void* d_out, int out_size) {
    const float* y    = (const float*)d_in[0];
    const float* Ic   = (const float*)d_in[1];
    const float* C    = (const float*)d_in[2];
    const float* gNa  = (const float*)d_in[3];
    const float* ENa  = (const float*)d_in[4];
    const float* gK   = (const float*)d_in[5];
    const float* EK   = (const float*)d_in[6];
    const float* gL   = (const float*)d_in[7];
    const float* EL   = (const float*)d_in[8];
    const float* minf = (const float*)d_in[9];
    const float* taum = (const float*)d_in[10];
    const float* hinf = (const float*)d_in[11];
    const float* tauh = (const float*)d_in[12];
    const float* ninf = (const float*)d_in[13];
    const float* taun = (const float*)d_in[14];
    const float* gC   = (const float*)d_in[15];

    float* out_ydot = (float*)d_out;
    float* out_J    = out_ydot + BATCH * E4;

    hh_fused_kernel<<<YBLOCKS + JBLOCKS, 256>>>(
        y, Ic, C, gNa, ENa, gK, EK, gL, EL,
        minf, taum, hinf, tauh, ninf, taun, gC,
        out_ydot, out_J);
}

// round 10
// speedup vs baseline: 1.0440x; 1.0440x over previous
#include <cuda_runtime.h>

// Inputs (metadata order):
// 0: y (B,4N) f32 | 1: Ic (B,) | 2: C (N,) | 3: g_Na | 4: E_Na | 5: g_K | 6: E_K
// 7: g_L | 8: E_L | 9: m_inf | 10: tau_m | 11: h_inf | 12: tau_h | 13: n_inf
// 14: tau_n | 15: g_C (N,N)
// Output: ydot (B,4N) followed by J (B,4N,4N), f32.

#define BATCH 256
#define NN    128   // N
#define E4    512   // 4*N
#define BPB   2     // batches per ydot block (kept small -> low reg pressure)
#define YBLOCKS (BATCH / BPB)          // 128 ydot-role blocks (scheduled first)
#define JBLOCKS 16384                  // 16,777,216 float4 / 1024 per block

// ---------------------------------------------------------------------------
// streaming 128-bit store (evict-first: J is write-once)
// ---------------------------------------------------------------------------
__device__ __forceinline__ void stg_cs(float4* p, float4 v) {
    asm volatile("st.global.cs.v4.f32 [%0], {%1, %2, %3, %4};"
                 :: "l"(p), "f"(v.x), "f"(v.y), "f"(v.z), "f"(v.w)
                 : "memory");
}

// ===========================================================================
// ONE fused kernel.
//   blockIdx < YBLOCKS  : ydot role — coupling dot, ydot output, AND the
//                         diagonal float4s of J (address-disjoint from the
//                         jfill role's writes).
//   blockIdx >= YBLOCKS : jfill role — streams all NON-diagonal float4s of J.
// NO __launch_bounds__ min-blocks clause: forcing 32 regs made the ydot role
// spill to local memory last round (+17us tail).  Regs float (~40-48).
// ===========================================================================
__global__ void __launch_bounds__(256) hh_fused_kernel(
    const float* __restrict__ y, const float* __restrict__ Ic,
    const float* __restrict__ C,
    const float* __restrict__ gNa, const float* __restrict__ ENa,
    const float* __restrict__ gK,  const float* __restrict__ EK,
    const float* __restrict__ gL,  const float* __restrict__ EL,
    const float* __restrict__ minf, const float* __restrict__ taum,
    const float* __restrict__ hinf, const float* __restrict__ tauh,
    const float* __restrict__ ninf, const float* __restrict__ taun,
    const float* __restrict__ gC,
    float* __restrict__ out_ydot,
    float* __restrict__ out_J)
{
    __shared__ float Gt[NN][33];       // padded gC column tile
    __shared__ float Wj[NN];           // invC[j]
    __shared__ float WVs[BPB][NN];     // invC[j] * V_b[j]
    __shared__ float red[4];

    int tid = threadIdx.x;

    if (blockIdx.x >= YBLOCKS) {
        // ------------------------------------------------------------------
        // jfill role: 1024 float4s per block, 4 coalesced stores per thread.
        // float4-idx layout: j = idx & 127; r = (idx>>7) & 511; b = idx>>16.
        // ------------------------------------------------------------------
        int base = (blockIdx.x - YBLOCKS) * 1024 + tid;
        int j = base & (NN - 1);
        float invCj = 1.0f / C[j];
        float4* out = reinterpret_cast<float4*>(out_J);

        #pragma unroll
        for (int k = 0; k < 4; k++) {
            int idx = base + k * 256;
            int r = (idx >> 7) & (E4 - 1);
            int rt = r & 3;          // warp-uniform
            int i  = r >> 2;

            float4 v = make_float4(0.f, 0.f, 0.f, 0.f);
            if (rt == 0)
                v.x = -gC[i * NN + j] * invCj;

            if (i != j)              // diagonal quad owned by ydot role
                stg_cs(out + idx, v);
        }
        return;
    }

    // ----------------------------------------------------------------------
    // ydot role: BPB batches per block.  All 256 threads help stage gC;
    // threads 0..127 own one neuron each.
    // ----------------------------------------------------------------------
    int b0 = blockIdx.x * BPB;
    int i  = tid;                    // neuron id (valid for tid < 128)
    int lane = tid & 31;
    int w8   = tid >> 5;             // warp id 0..7

    float invCi = 0.f;
    float V[BPB], m[BPB], h[BPB], n[BPB];

    if (tid < NN) {
        invCi = 1.0f / C[i];
        Wj[i] = invCi;
        #pragma unroll
        for (int bb = 0; bb < BPB; bb++) {
            float4 y4 = reinterpret_cast<const float4*>(y)[(b0 + bb) * NN + i];
            V[bb] = y4.x; m[bb] = y4.y; h[bb] = y4.z; n[bb] = y4.w;
            WVs[bb][i] = invCi * y4.x;
        }
    }
    __syncthreads();

    float rs = 0.0f;                 // sum_j g[i][j] * invC[j]  (batch-indep)
    float gv[BPB];
    #pragma unroll
    for (int bb = 0; bb < BPB; bb++) gv[bb] = 0.f;

    #pragma unroll
    for (int t = 0; t < 4; t++) {
        // all 256 threads stage columns [32t, 32t+32): 8 warps x 16 rows
        #pragma unroll 4
        for (int k = 0; k < 16; k++) {
            int row = k * 8 + w8;
            Gt[row][lane] = gC[row * NN + t * 32 + lane];
        }
        __syncthreads();

        if (tid < NN) {
            #pragma unroll 4
            for (int jj = 0; jj < 32; jj++) {
                float g = Gt[i][jj];
                int j = t * 32 + jj;
                rs += g * Wj[j];
                #pragma unroll
                for (int bb = 0; bb < BPB; bb++)
                    gv[bb] += g * WVs[bb][j];
            }
        }
        __syncthreads();
    }

    // block-reduce rs over threads 0..127 -> S (deterministic), broadcast
    if (tid < NN) {
        float tr = rs;
        #pragma unroll
        for (int o2 = 16; o2 > 0; o2 >>= 1)
            tr += __shfl_xor_sync(0xFFFFFFFFu, tr, o2);
        if (lane == 0) red[w8] = tr;       // w8 in 0..3 for tid<128
    }
    __syncthreads();

    if (tid >= NN) return;

    float S = red[0] + red[1] + red[2] + red[3];

    float ga = gNa[i], gk = gK[i], gl = gL[i];
    float eNa = ENa[i], eK = EK[i], eL = EL[i];
    float mi = minf[i], hi = hinf[i], ni = ninf[i];
    float itm = 1.0f / taum[i], ith = 1.0f / tauh[i], itn = 1.0f / taun[i];
    float gdiag = gC[i * NN + i];
    float4* outJ4 = reinterpret_cast<float4*>(out_J);

    #pragma unroll
    for (int bb = 0; bb < BPB; bb++) {
        int b = b0 + bb;
        float Vb = V[bb], mb = m[bb], hb = h[bb], nb = n[bb];
        float acc = Vb * rs - gv[bb];
        float m2 = mb * mb, m3 = m2 * mb;
        float n2 = nb * nb, n3 = n2 * nb, n4 = n3 * nb;
        float dNa = Vb - eNa, dK = Vb - eK;

        float Vdot = invCi * (-ga * m3 * hb * dNa
                              - gk * n4 * dK
                              - gl * (Vb - eL)
                              + Ic[b]) + acc;
        float4 o;
        o.x = Vdot;
        o.y = (mi - mb) * itm;
        o.z = (hi - hb) * ith;
        o.w = (ni - nb) * itn;
        reinterpret_cast<float4*>(out_ydot)[b * NN + i] = o;

        // ---- diagonal float4s of J for (b, i): rows 4i..4i+3, col-quad i ----
        int idx0 = b * (E4 * NN) + (4 * i) * NN + i;   // V row
        float4 dv;
        dv.x = -gdiag * invCi + S + invCi * (-gl - ga * hb * m3 - gk * n4);
        dv.y = -invCi * (3.0f * ga * hb * m2 * dNa);
        dv.z = -invCi * (ga * m3 * dNa);
        dv.w = -invCi * (4.0f * gk * n3 * dK);
        outJ4[idx0]            = dv;
        outJ4[idx0 + NN]       = make_float4(0.f, -itm, 0.f, 0.f);  // m row
        outJ4[idx0 + 2 * NN]   = make_float4(0.f, 0.f, -ith, 0.f);  // h row
        outJ4[idx0 + 3 * NN]   = make_float4(0.f, 0.f, 0.f, -itn);  // n row
    }
}

// ---------------------------------------------------------------------------
extern "C" void kernel_launch(void* const* d_in, const int* in_sizes, int n_in,
                              void* d_out, int out_size) {
    const float* y    = (const float*)d_in[0];
    const float* Ic   = (const float*)d_in[1];
    const float* C    = (const float*)d_in[2];
    const float* gNa  = (const float*)d_in[3];
    const float* ENa  = (const float*)d_in[4];
    const float* gK   = (const float*)d_in[5];
    const float* EK   = (const float*)d_in[6];
    const float* gL   = (const float*)d_in[7];
    const float* EL   = (const float*)d_in[8];
    const float* minf = (const float*)d_in[9];
    const float* taum = (const float*)d_in[10];
    const float* hinf = (const float*)d_in[11];
    const float* tauh = (const float*)d_in[12];
    const float* ninf = (const float*)d_in[13];
    const float* taun = (const float*)d_in[14];
    const float* gC   = (const float*)d_in[15];

    float* out_ydot = (float*)d_out;
    float* out_J    = out_ydot + BATCH * E4;

    hh_fused_kernel<<<YBLOCKS + JBLOCKS, 256>>>(
        y, Ic, C, gNa, ENa, gK, EK, gL, EL,
        minf, taum, hinf, tauh, ninf, taun, gC,
        out_ydot, out_J);
}